// round 1
// baseline (speedup 1.0000x reference)
#include <cuda_runtime.h>
#include <cuda_bf16.h>
#include <cstdint>

// Problem dims (fixed by the dataset)
#define NN   8192   // nodes
#define D0   128
#define D1   256
#define D2   256
#define QH   128
#define EPSV 1e-5f

// ---------------- scratch (static device allocations: allowed) --------------
__device__ float g_x[NN * D0];          // normalized state, later reused for Q-hidden
__device__ float g_y[NN * D1];          // XW products
__device__ float g_h[NN * D2];          // hidden after A-gemm
__device__ float g_part[64 * 2 * D0];   // BN partial sums
__device__ float g_mean[D0];
__device__ float g_rstd[D0];

// ---------------- batchnorm ------------------------------------------------
// Stage 1: 64 blocks, each reduces 128 rows; 128 threads = one per column.
__global__ void bn_partial_kernel(const float* __restrict__ state) {
    int c = threadIdx.x;           // column 0..127
    int b = blockIdx.x;            // row-chunk 0..63
    int r0 = b * (NN / 64);
    float s = 0.f, s2 = 0.f;
    #pragma unroll 4
    for (int r = 0; r < NN / 64; ++r) {
        float v = state[(size_t)(r0 + r) * D0 + c];
        s  += v;
        s2 += v * v;
    }
    g_part[b * 2 * D0 + c]      = s;
    g_part[b * 2 * D0 + D0 + c] = s2;
}

// Stage 2: single block, deterministic finalize.
__global__ void bn_final_kernel() {
    int c = threadIdx.x;
    float s = 0.f, s2 = 0.f;
    #pragma unroll
    for (int b = 0; b < 64; ++b) {
        s  += g_part[b * 2 * D0 + c];
        s2 += g_part[b * 2 * D0 + D0 + c];
    }
    float mean = s * (1.0f / NN);
    float var  = s2 * (1.0f / NN) - mean * mean;
    g_mean[c] = mean;
    g_rstd[c] = rsqrtf(var + EPSV);
}

__global__ void bn_apply_kernel(const float* __restrict__ state,
                                const float* __restrict__ gamma,
                                const float* __restrict__ beta) {
    int i = blockIdx.x * blockDim.x + threadIdx.x;   // 0 .. NN*D0-1
    int c = i & (D0 - 1);
    float v = state[i];
    g_x[i] = (v - g_mean[c]) * g_rstd[c] * gamma[c] + beta[c];
}

// ---------------- generic tiled SGEMM with fused epilogue -------------------
// C[M,N] = op(A[M,K] @ B[K,N] (+bias) (relu))   row-major everything.
// BM=BN=64, BK=16, 256 threads, 4x4 register tile. All dims divide evenly.
template<bool BIAS, bool RELU>
__global__ void sgemm_kernel(const float* __restrict__ A,
                             const float* __restrict__ B,
                             const float* __restrict__ bias,
                             float* __restrict__ C,
                             int M, int N, int K) {
    constexpr int BM = 64, BN = 64, BK = 16, TM = 4, TN = 4;
    __shared__ float As[BK][BM];
    __shared__ float Bs[BK][BN];

    const int tid = threadIdx.x;
    const int tx = tid % (BN / TN);          // 0..15
    const int ty = tid / (BN / TN);          // 0..15
    const int rowBase = blockIdx.y * BM;
    const int colBase = blockIdx.x * BN;

    // A-tile load mapping: one float4 along K per thread
    const int aRow = tid / (BK / 4);         // 0..63
    const int aCol = (tid % (BK / 4)) * 4;   // 0,4,8,12
    // B-tile load mapping: one float4 along N per thread
    const int bRow = tid / (BN / 4);         // 0..15
    const int bCol = (tid % (BN / 4)) * 4;   // 0..60

    float acc[TM][TN] = {};

    for (int k0 = 0; k0 < K; k0 += BK) {
        float4 av = *(const float4*)(A + (size_t)(rowBase + aRow) * K + k0 + aCol);
        As[aCol + 0][aRow] = av.x;
        As[aCol + 1][aRow] = av.y;
        As[aCol + 2][aRow] = av.z;
        As[aCol + 3][aRow] = av.w;
        float4 bv = *(const float4*)(B + (size_t)(k0 + bRow) * N + colBase + bCol);
        *(float4*)&Bs[bRow][bCol] = bv;
        __syncthreads();

        #pragma unroll
        for (int k = 0; k < BK; ++k) {
            float a[TM], b[TN];
            float4 a4 = *(const float4*)&As[k][ty * TM];
            a[0] = a4.x; a[1] = a4.y; a[2] = a4.z; a[3] = a4.w;
            float4 b4 = *(const float4*)&Bs[k][tx * TN];
            b[0] = b4.x; b[1] = b4.y; b[2] = b4.z; b[3] = b4.w;
            #pragma unroll
            for (int i = 0; i < TM; ++i)
                #pragma unroll
                for (int j = 0; j < TN; ++j)
                    acc[i][j] = fmaf(a[i], b[j], acc[i][j]);
        }
        __syncthreads();
    }

    #pragma unroll
    for (int i = 0; i < TM; ++i) {
        int r = rowBase + ty * TM + i;
        #pragma unroll
        for (int j = 0; j < TN; ++j) {
            int c = colBase + tx * TN + j;
            float v = acc[i][j];
            if (BIAS) v += bias[c];
            if (RELU) v = fmaxf(v, 0.f);
            C[(size_t)r * N + c] = v;
        }
    }
}

// ---------------- final Q output: out[r] = dot(T[r,:], Wq2) + bq2 ----------
__global__ void qout_kernel(const float* __restrict__ T,
                            const float* __restrict__ Wq2,
                            const float* __restrict__ bq2,
                            float* __restrict__ out) {
    int warp = threadIdx.x >> 5;
    int lane = threadIdx.x & 31;
    int row  = blockIdx.x * 8 + warp;
    const float* t = T + (size_t)row * QH;
    float s = 0.f;
    #pragma unroll
    for (int k = lane; k < QH; k += 32) s += t[k] * Wq2[k];
    #pragma unroll
    for (int o = 16; o; o >>= 1) s += __shfl_xor_sync(0xffffffffu, s, o);
    if (lane == 0) out[row] = s + bq2[0];
}

// ---------------- launcher --------------------------------------------------
extern "C" void kernel_launch(void* const* d_in, const int* in_sizes, int n_in,
                              void* d_out, int out_size) {
    const float* state = (const float*)d_in[0];
    const float* adj   = (const float*)d_in[1];
    const float* gamma = (const float*)d_in[2];
    const float* beta  = (const float*)d_in[3];
    const float* W1    = (const float*)d_in[4];
    const float* b1    = (const float*)d_in[5];
    const float* W2    = (const float*)d_in[6];
    const float* b2    = (const float*)d_in[7];
    const float* Wq1   = (const float*)d_in[8];
    const float* bq1   = (const float*)d_in[9];
    const float* Wq2   = (const float*)d_in[10];
    const float* bq2   = (const float*)d_in[11];
    float* out = (float*)d_out;

    float *gx, *gy, *gh;
    cudaGetSymbolAddress((void**)&gx, g_x);
    cudaGetSymbolAddress((void**)&gy, g_y);
    cudaGetSymbolAddress((void**)&gh, g_h);

    // BatchNorm
    bn_partial_kernel<<<64, D0>>>(state);
    bn_final_kernel<<<1, D0>>>();
    bn_apply_kernel<<<(NN * D0) / 256, 256>>>(state, gamma, beta);

    // G1: g_y = x @ W1                      [8192,128]@[128,256]
    sgemm_kernel<false, false><<<dim3(D1 / 64, NN / 64), 256>>>(gx, W1, nullptr, gy, NN, D1, D0);
    // G2: g_h = relu(A @ g_y + b1)          [8192,8192]@[8192,256]
    sgemm_kernel<true, true><<<dim3(D1 / 64, NN / 64), 256>>>(adj, gy, b1, gh, NN, D1, NN);
    // G3: g_y = g_h @ W2                    [8192,256]@[256,256]
    sgemm_kernel<false, false><<<dim3(D2 / 64, NN / 64), 256>>>(gh, W2, nullptr, gy, NN, D2, D1);
    // G4: g_h = relu(A @ g_y + b2)          [8192,8192]@[8192,256]
    sgemm_kernel<true, true><<<dim3(D2 / 64, NN / 64), 256>>>(adj, gy, b2, gh, NN, D2, NN);
    // G5a: g_x = relu(g_h @ Wq1 + bq1)      [8192,256]@[256,128]
    sgemm_kernel<true, true><<<dim3(QH / 64, NN / 64), 256>>>(gh, Wq1, bq1, gx, NN, QH, D2);
    // G5b: out = g_x @ Wq2 + bq2            [8192,128]@[128,1]
    qout_kernel<<<NN / 8, 256>>>(gx, Wq2, bq2, out);
}

// round 3
// speedup vs baseline: 2.5688x; 2.5688x over previous
#include <cuda_runtime.h>
#include <cuda_bf16.h>
#include <cstdint>

// Problem dims (fixed by the dataset)
#define NN   8192
#define D0   128
#define D1   256
#define D2   256
#define QH   128
#define EPSV 1e-5f

// big-GEMM tiling (mma.sync path)
#define BM    64
#define BN    256
#define BK    32
#define NIT   (NN / BK)            // 256
#define PITCH 80                   // bytes per 32-bf16 smem row (conflict-free for ldmatrix)
#define SA_SZ (64 * PITCH)         // 5120 B per A matrix tile
#define SB_SZ (256 * PITCH)        // 20480 B per B matrix tile
#define STAGE_SZ (2 * SA_SZ + 2 * SB_SZ)   // 51200
#define NSTAGE 3
#define DSMEM_SZ (NSTAGE * STAGE_SZ)       // 153600

// ---------------- scratch (static device allocations: allowed) --------------
__device__ float g_x[NN * D0];
__device__ float g_y[NN * D1];
__device__ float g_h[NN * D2];
__device__ float g_part[64 * 2 * D0];
__device__ float g_mean[D0];
__device__ float g_rstd[D0];
__device__ __nv_bfloat16 g_Ahi[(size_t)NN * NN];
__device__ __nv_bfloat16 g_Alo[(size_t)NN * NN];
__device__ __nv_bfloat16 g_Bhi[(size_t)D1 * NN];   // Y transposed: [256, 8192]
__device__ __nv_bfloat16 g_Blo[(size_t)D1 * NN];

// ---------------- PTX helpers (baseline ISA only) ---------------------------
__device__ __forceinline__ uint32_t smem_u32(const void* p) {
    uint32_t a;
    asm("{ .reg .u64 t; cvta.to.shared.u64 t, %1; cvt.u32.u64 %0, t; }" : "=r"(a) : "l"(p));
    return a;
}
__device__ __forceinline__ void cp_async16(uint32_t dst, const void* src) {
    asm volatile("cp.async.cg.shared.global [%0], [%1], 16;" :: "r"(dst), "l"(src) : "memory");
}
__device__ __forceinline__ void ldsm4(uint32_t& r0, uint32_t& r1, uint32_t& r2, uint32_t& r3,
                                      uint32_t a) {
    asm volatile("ldmatrix.sync.aligned.m8n8.x4.shared.b16 {%0,%1,%2,%3}, [%4];"
                 : "=r"(r0), "=r"(r1), "=r"(r2), "=r"(r3) : "r"(a));
}
__device__ __forceinline__ void mma_bf16(float* c, const uint32_t* a, const uint32_t* b) {
    asm volatile("mma.sync.aligned.m16n8k16.row.col.f32.bf16.bf16.f32 "
                 "{%0,%1,%2,%3}, {%4,%5,%6,%7}, {%8,%9}, {%0,%1,%2,%3};"
                 : "+f"(c[0]), "+f"(c[1]), "+f"(c[2]), "+f"(c[3])
                 : "r"(a[0]), "r"(a[1]), "r"(a[2]), "r"(a[3]), "r"(b[0]), "r"(b[1]));
}

// ---------------- batchnorm ------------------------------------------------
__global__ void bn_partial_kernel(const float* __restrict__ state) {
    int c = threadIdx.x, b = blockIdx.x;
    int r0 = b * (NN / 64);
    float s = 0.f, s2 = 0.f;
    #pragma unroll 4
    for (int r = 0; r < NN / 64; ++r) {
        float v = state[(size_t)(r0 + r) * D0 + c];
        s += v; s2 += v * v;
    }
    g_part[b * 2 * D0 + c]      = s;
    g_part[b * 2 * D0 + D0 + c] = s2;
}
__global__ void bn_final_kernel() {
    int c = threadIdx.x;
    float s = 0.f, s2 = 0.f;
    #pragma unroll
    for (int b = 0; b < 64; ++b) {
        s  += g_part[b * 2 * D0 + c];
        s2 += g_part[b * 2 * D0 + D0 + c];
    }
    float mean = s * (1.0f / NN);
    float var  = s2 * (1.0f / NN) - mean * mean;
    g_mean[c] = mean;
    g_rstd[c] = rsqrtf(var + EPSV);
}
__global__ void bn_apply_kernel(const float* __restrict__ state,
                                const float* __restrict__ gamma,
                                const float* __restrict__ beta) {
    int i = blockIdx.x * blockDim.x + threadIdx.x;
    int c = i & (D0 - 1);
    float v = state[i];
    g_x[i] = (v - g_mean[c]) * g_rstd[c] * gamma[c] + beta[c];
}

// ---------------- A -> bf16 hi/lo split -------------------------------------
__global__ void convA_kernel(const float* __restrict__ A) {
    size_t i = ((size_t)blockIdx.x * blockDim.x + threadIdx.x) * 4;
    float4 v = *(const float4*)(A + i);
    float f[4] = {v.x, v.y, v.z, v.w};
    union { __nv_bfloat16 h[4]; unsigned long long u; } uh, ul;
    #pragma unroll
    for (int k = 0; k < 4; ++k) {
        uh.h[k] = __float2bfloat16(f[k]);
        ul.h[k] = __float2bfloat16(f[k] - __bfloat162float(uh.h[k]));
    }
    *(unsigned long long*)(g_Ahi + i) = uh.u;
    *(unsigned long long*)(g_Alo + i) = ul.u;
}

// ---------------- Y [NN,256] fp32 -> transposed bf16 hi/lo [256, NN] --------
__global__ void convT_kernel(const float* __restrict__ Y) {
    __shared__ float tile[32][33];
    int n0 = blockIdx.x * 32;
    int c0 = blockIdx.y * 32;
    int tx = threadIdx.x, ty = threadIdx.y;   // 32 x 8
    #pragma unroll
    for (int r = 0; r < 32; r += 8)
        tile[ty + r][tx] = Y[(size_t)(n0 + ty + r) * 256 + c0 + tx];
    __syncthreads();
    #pragma unroll
    for (int r = 0; r < 32; r += 8) {
        float v = tile[tx][ty + r];
        __nv_bfloat16 hi = __float2bfloat16(v);
        __nv_bfloat16 lo = __float2bfloat16(v - __bfloat162float(hi));
        size_t o = (size_t)(c0 + ty + r) * NN + n0 + tx;
        g_Bhi[o] = hi;
        g_Blo[o] = lo;
    }
}

// ---------------- big GEMM via mma.sync (split-precision bf16) --------------
// C[8192,256] = relu(A @ B^T + bias).  A hi/lo [NN,NN] row-major;
// B hi/lo [256,NN] K-major.  Tile 64x256xBK32, 8 warps, 3-stage cp.async.
__global__ void __launch_bounds__(256, 1)
bigmm_kernel(const __nv_bfloat16* __restrict__ Ahi, const __nv_bfloat16* __restrict__ Alo,
             const __nv_bfloat16* __restrict__ Bhi, const __nv_bfloat16* __restrict__ Blo,
             const float* __restrict__ bias, float* __restrict__ C) {
    extern __shared__ char sm[];
    const uint32_t sbase = smem_u32(sm);
    const int tid = threadIdx.x;
    const int m0  = blockIdx.x * BM;

    // ---- load mapping: 1 chunk A(hi,lo), 4 rows B(hi,lo) per thread ----
    const int lrow = tid >> 2;                 // 0..63
    const int lchk = tid & 3;                  // 0..3
    const __nv_bfloat16* gAh = Ahi + (size_t)(m0 + lrow) * NN + lchk * 8;
    const __nv_bfloat16* gAl = Alo + (size_t)(m0 + lrow) * NN + lchk * 8;
    const __nv_bfloat16* gBh = Bhi + (size_t)lrow * NN + lchk * 8;
    const __nv_bfloat16* gBl = Blo + (size_t)lrow * NN + lchk * 8;
    const uint32_t sAoff = (uint32_t)lrow * PITCH + lchk * 16;

    // ---- compute mapping ----
    const int wid = tid >> 5, lane = tid & 31;
    const int wm = wid & 1;                    // 0..1 (32 rows each)
    const int wn = wid >> 1;                   // 0..3 (64 cols each)
    const uint32_t aLane = (uint32_t)(wm * 32 + (lane & 15)) * PITCH + (lane >> 4) * 16;
    const uint32_t bLane = (uint32_t)(wn * 64 + ((lane >> 4) << 3) + (lane & 7)) * PITCH
                           + ((lane >> 3) & 1) * 16;

    float acc[2][8][4];
    #pragma unroll
    for (int mt = 0; mt < 2; ++mt)
        #pragma unroll
        for (int nt = 0; nt < 8; ++nt)
            #pragma unroll
            for (int q = 0; q < 4; ++q) acc[mt][nt][q] = 0.f;

    auto LOAD = [&](int s, int j) {
        uint32_t sb = sbase + s * STAGE_SZ;
        size_t k = (size_t)j * BK;
        cp_async16(sb + sAoff,          gAh + k);
        cp_async16(sb + SA_SZ + sAoff,  gAl + k);
        #pragma unroll
        for (int i = 0; i < 4; ++i) {
            size_t g = k + (size_t)i * 64 * NN;
            uint32_t d = sb + 2 * SA_SZ + (uint32_t)(lrow + 64 * i) * PITCH + lchk * 16;
            cp_async16(d,         gBh + g);
            cp_async16(d + SB_SZ, gBl + g);
        }
        asm volatile("cp.async.commit_group;" ::: "memory");
    };

    LOAD(0, 0);
    LOAD(1, 1);

    int s = 0, ls = 2;
    for (int j = 0; j < NIT; ++j) {
        if (j + 2 < NIT) {
            asm volatile("cp.async.wait_group 1;" ::: "memory");
        } else {
            asm volatile("cp.async.wait_group 0;" ::: "memory");
        }
        __syncthreads();
        if (j + 2 < NIT) {
            LOAD(ls, j + 2);
            if (++ls == NSTAGE) ls = 0;
        }

        // ---- compute stage s ----
        const uint32_t sb = sbase + s * STAGE_SZ;
        #pragma unroll
        for (int kh = 0; kh < 2; ++kh) {
            uint32_t ah[2][4], al[2][4], bh[8][2], bl[8][2];
            #pragma unroll
            for (int mt = 0; mt < 2; ++mt) {
                uint32_t ad = sb + aLane + mt * (16 * PITCH) + kh * 32;
                ldsm4(ah[mt][0], ah[mt][1], ah[mt][2], ah[mt][3], ad);
                ldsm4(al[mt][0], al[mt][1], al[mt][2], al[mt][3], ad + SA_SZ);
            }
            #pragma unroll
            for (int p = 0; p < 4; ++p) {
                uint32_t bd = sb + 2 * SA_SZ + bLane + p * (16 * PITCH) + kh * 32;
                uint32_t r0, r1, r2, r3;
                ldsm4(r0, r1, r2, r3, bd);
                bh[2 * p][0] = r0; bh[2 * p][1] = r1;
                bh[2 * p + 1][0] = r2; bh[2 * p + 1][1] = r3;
                ldsm4(r0, r1, r2, r3, bd + SB_SZ);
                bl[2 * p][0] = r0; bl[2 * p][1] = r1;
                bl[2 * p + 1][0] = r2; bl[2 * p + 1][1] = r3;
            }
            #pragma unroll
            for (int mt = 0; mt < 2; ++mt)
                #pragma unroll
                for (int nt = 0; nt < 8; ++nt)
                    mma_bf16(acc[mt][nt], ah[mt], bh[nt]);
            #pragma unroll
            for (int mt = 0; mt < 2; ++mt)
                #pragma unroll
                for (int nt = 0; nt < 8; ++nt)
                    mma_bf16(acc[mt][nt], ah[mt], bl[nt]);
            #pragma unroll
            for (int mt = 0; mt < 2; ++mt)
                #pragma unroll
                for (int nt = 0; nt < 8; ++nt)
                    mma_bf16(acc[mt][nt], al[mt], bh[nt]);
        }
        if (++s == NSTAGE) s = 0;
    }

    // ---- epilogue: bias + relu + store ----
    #pragma unroll
    for (int mt = 0; mt < 2; ++mt) {
        #pragma unroll
        for (int nt = 0; nt < 8; ++nt) {
            int r = m0 + wm * 32 + mt * 16 + (lane >> 2);
            int c = wn * 64 + nt * 8 + (lane & 3) * 2;
            float b0 = bias[c], b1 = bias[c + 1];
            float2 v0;
            v0.x = fmaxf(acc[mt][nt][0] + b0, 0.f);
            v0.y = fmaxf(acc[mt][nt][1] + b1, 0.f);
            *(float2*)(C + (size_t)r * 256 + c) = v0;
            float2 v1;
            v1.x = fmaxf(acc[mt][nt][2] + b0, 0.f);
            v1.y = fmaxf(acc[mt][nt][3] + b1, 0.f);
            *(float2*)(C + (size_t)(r + 8) * 256 + c) = v1;
        }
    }
}

// ---------------- small fp32 SGEMM (fused bias/relu) ------------------------
template<bool BIAS, bool RELU>
__global__ void sgemm_kernel(const float* __restrict__ A,
                             const float* __restrict__ B,
                             const float* __restrict__ bias,
                             float* __restrict__ C,
                             int M, int N, int K) {
    constexpr int TBM = 64, TBN = 64, TBK = 16, TM = 4, TN = 4;
    __shared__ float As[TBK][TBM];
    __shared__ float Bs[TBK][TBN];
    const int tid = threadIdx.x;
    const int tx = tid % (TBN / TN);
    const int ty = tid / (TBN / TN);
    const int rowBase = blockIdx.y * TBM;
    const int colBase = blockIdx.x * TBN;
    const int aRow = tid / (TBK / 4);
    const int aCol = (tid % (TBK / 4)) * 4;
    const int bRow = tid / (TBN / 4);
    const int bCol = (tid % (TBN / 4)) * 4;
    float acc[TM][TN] = {};
    for (int k0 = 0; k0 < K; k0 += TBK) {
        float4 av = *(const float4*)(A + (size_t)(rowBase + aRow) * K + k0 + aCol);
        As[aCol + 0][aRow] = av.x; As[aCol + 1][aRow] = av.y;
        As[aCol + 2][aRow] = av.z; As[aCol + 3][aRow] = av.w;
        float4 bv = *(const float4*)(B + (size_t)(k0 + bRow) * N + colBase + bCol);
        *(float4*)&Bs[bRow][bCol] = bv;
        __syncthreads();
        #pragma unroll
        for (int k = 0; k < TBK; ++k) {
            float4 a4 = *(const float4*)&As[k][ty * TM];
            float4 b4 = *(const float4*)&Bs[k][tx * TN];
            float a[TM] = {a4.x, a4.y, a4.z, a4.w};
            float b[TN] = {b4.x, b4.y, b4.z, b4.w};
            #pragma unroll
            for (int i = 0; i < TM; ++i)
                #pragma unroll
                for (int j = 0; j < TN; ++j)
                    acc[i][j] = fmaf(a[i], b[j], acc[i][j]);
        }
        __syncthreads();
    }
    #pragma unroll
    for (int i = 0; i < TM; ++i) {
        int r = rowBase + ty * TM + i;
        #pragma unroll
        for (int j = 0; j < TN; ++j) {
            int c = colBase + tx * TN + j;
            float v = acc[i][j];
            if (BIAS) v += bias[c];
            if (RELU) v = fmaxf(v, 0.f);
            C[(size_t)r * N + c] = v;
        }
    }
}

// ---------------- final Q output --------------------------------------------
__global__ void qout_kernel(const float* __restrict__ T,
                            const float* __restrict__ Wq2,
                            const float* __restrict__ bq2,
                            float* __restrict__ out) {
    int warp = threadIdx.x >> 5;
    int lane = threadIdx.x & 31;
    int row  = blockIdx.x * 8 + warp;
    const float* t = T + (size_t)row * QH;
    float s = 0.f;
    #pragma unroll
    for (int k = lane; k < QH; k += 32) s += t[k] * Wq2[k];
    #pragma unroll
    for (int o = 16; o; o >>= 1) s += __shfl_xor_sync(0xffffffffu, s, o);
    if (lane == 0) out[row] = s + bq2[0];
}

// ---------------- launcher --------------------------------------------------
extern "C" void kernel_launch(void* const* d_in, const int* in_sizes, int n_in,
                              void* d_out, int out_size) {
    const float* state = (const float*)d_in[0];
    const float* adj   = (const float*)d_in[1];
    const float* gamma = (const float*)d_in[2];
    const float* beta  = (const float*)d_in[3];
    const float* W1    = (const float*)d_in[4];
    const float* b1    = (const float*)d_in[5];
    const float* W2    = (const float*)d_in[6];
    const float* b2    = (const float*)d_in[7];
    const float* Wq1   = (const float*)d_in[8];
    const float* bq1   = (const float*)d_in[9];
    const float* Wq2   = (const float*)d_in[10];
    const float* bq2   = (const float*)d_in[11];
    float* out = (float*)d_out;

    float *gx, *gy, *gh;
    __nv_bfloat16 *gAhi, *gAlo, *gBhi, *gBlo;
    cudaGetSymbolAddress((void**)&gx, g_x);
    cudaGetSymbolAddress((void**)&gy, g_y);
    cudaGetSymbolAddress((void**)&gh, g_h);
    cudaGetSymbolAddress((void**)&gAhi, g_Ahi);
    cudaGetSymbolAddress((void**)&gAlo, g_Alo);
    cudaGetSymbolAddress((void**)&gBhi, g_Bhi);
    cudaGetSymbolAddress((void**)&gBlo, g_Blo);

    cudaFuncSetAttribute(bigmm_kernel, cudaFuncAttributeMaxDynamicSharedMemorySize, DSMEM_SZ);

    // A -> bf16 hi/lo (used by both big GEMMs)
    convA_kernel<<<(size_t)NN * NN / 4 / 256, 256>>>(adj);

    // BatchNorm
    bn_partial_kernel<<<64, D0>>>(state);
    bn_final_kernel<<<1, D0>>>();
    bn_apply_kernel<<<(NN * D0) / 256, 256>>>(state, gamma, beta);

    // Y1 = x @ W1 (fp32), then split+transpose to bf16
    sgemm_kernel<false, false><<<dim3(D1 / 64, NN / 64), 256>>>(gx, W1, nullptr, gy, NN, D1, D0);
    convT_kernel<<<dim3(NN / 32, 256 / 32), dim3(32, 8)>>>(gy);

    // h1 = relu(A @ Y1 + b1)   — tensor cores (mma.sync)
    bigmm_kernel<<<NN / BM, 256, DSMEM_SZ>>>(gAhi, gAlo, gBhi, gBlo, b1, gh);

    // Y2 = h1 @ W2 (fp32), split+transpose
    sgemm_kernel<false, false><<<dim3(D2 / 64, NN / 64), 256>>>(gh, W2, nullptr, gy, NN, D2, D1);
    convT_kernel<<<dim3(NN / 32, 256 / 32), dim3(32, 8)>>>(gy);

    // h2 = relu(A @ Y2 + b2)   — tensor cores (mma.sync)
    bigmm_kernel<<<NN / BM, 256, DSMEM_SZ>>>(gAhi, gAlo, gBhi, gBlo, b2, gh);

    // Q head
    sgemm_kernel<true, true><<<dim3(QH / 64, NN / 64), 256>>>(gh, Wq1, bq1, gx, NN, QH, D2);
    qout_kernel<<<NN / 8, 256>>>(gx, Wq2, bq2, out);
}